// round 10
// baseline (speedup 1.0000x reference)
#include <cuda_runtime.h>
#include <cstdint>

// Problem constants (fixed shapes)
#define VF    128            // V*F = 8*16
#define CCH   1024
#define HH    14
#define WW    14
#define NBOX  768
#define GG    8              // grid = OUT_SIZE+1
#define OUTS  7
#define CHT   32             // channels per block tile
#define TILES (CCH / CHT)    // 32
#define PSTR  130            // plane stride: span(<=126) + 2 pad, 130%32=2
#define SCALE (1.0f/16.0f)

#define ROI_BLOCKS   ((NBOX/2) * TILES)                  // 12288 (box PAIRS)
#define SNODE_BLOCKS ((VF * CCH) / 8)                    // 16384

#define ROI_COUNT   ((size_t)NBOX * CCH * OUTS * OUTS)   // 38,535,168
#define SNODE_OFF   (ROI_COUNT)
#define FAKE_OFF    (SNODE_OFF + (size_t)VF * CCH)       // 38,666,240

__device__ __forceinline__ void cp_async8(unsigned int smem_dst, const void* gmem_src) {
    asm volatile("cp.async.ca.shared.global [%0], [%1], 8;\n"
                 :: "r"(smem_dst), "l"(gmem_src) : "memory");
}

// Per-thread compute + warp store for one box. plane_w = plane slot base for
// this box; outs_w = warp's staging slice; dst = gmem dst for warp's 4 ch.
__device__ __forceinline__ void roi_compute_store(
    const float* __restrict__ plane_w,   // + (cw)*PSTR already applied by caller? no: slot base
    float* __restrict__ outs_w,          // outsm + cw*49
    float4* __restrict__ dst4,           // out + (n*CCH + c0 + cw)*49, as float4
    int cw, int lane,
    float bx1, float dxv, float by1, float dyv, int ry0)
{
    const int gx    = lane & 7;
    const int chsub = lane >> 3;

    const float xs0 = fminf(fmaf((float)gx, dxv, bx1), 13.0f);
    const float x0f = floorf(xs0);
    const float wx  = xs0 - x0f;

    const float* plx = plane_w + (cw + chsub) * PSTR + (int)x0f;
    float*       od  = outs_w + chsub * (OUTS*OUTS) + gx;

    int   curA = -1000;
    float a0 = 0.f, a1 = 0.f, b0 = 0.f, b1 = 0.f;
    float xs_prev = 0.f;

    #pragma unroll
    for (int gy = 0; gy < GG; ++gy) {
        const float ys  = fminf(fmaf((float)gy, dyv, by1), 13.0f);
        const float y0f = floorf(ys);
        const float wy  = ys - y0f;
        const int   rA  = (int)y0f - ry0;
        if (rA != curA) {                 // warp-uniform branch
            if (rA == curA + 1) { a0 = b0; a1 = b1; }
            else                { a0 = plx[rA*WW]; a1 = plx[rA*WW + 1]; }
            b0 = plx[rA*WW + WW]; b1 = plx[rA*WW + WW + 1];
            curA = rA;
        }
        const float top = fmaf(wx, a1 - a0, a0);
        const float bot = fmaf(wx, b1 - b0, b0);
        const float g   = fmaf(wy, bot - top, top);
        const float gr   = __shfl_down_sync(0xFFFFFFFFu, g, 1, 8);
        const float xsum = g + gr;
        if (gy > 0 && gx < OUTS)
            od[(gy-1) * OUTS] = 0.25f * (xs_prev + xsum);
        xs_prev = xsum;
    }
    __syncwarp();
    // warp-local staged -> gmem, 4ch*49 floats = 49 float4, 16B aligned
    const float4* src4 = (const float4*)outs_w;
    #pragma unroll
    for (int i = lane; i < 49; i += 32)
        dst4[i] = src4[i];
    __syncwarp();   // outs_w may be reused by caller for next box
}

// ---------------------------------------------------------------------------
// Fused kernel. Blocks [0, ROI_BLOCKS) each do RoIAlignAvg for a PAIR of
// boxes (double-buffered cp.async: box B's loads overlap box A's compute).
// Fully warp-independent: warp w owns channels 4w..4w+3. No __syncthreads.
// Remaining blocks do the s_node mean + fake_h_s slice.
// ---------------------------------------------------------------------------
__global__ __launch_bounds__(256, 5) void fused_kernel(
    const float* __restrict__ feat,
    const float* __restrict__ boxes,
    const int*   __restrict__ fidx,
    float*       __restrict__ out)
{
    extern __shared__ float sm[];

    if (blockIdx.x >= ROI_BLOCKS) {
        // ---------------- snode + fake_h_s branch -------------------------
        const int warp = threadIdx.x >> 5;
        const int lane = threadIdx.x & 31;
        const size_t planeidx = (size_t)(blockIdx.x - ROI_BLOCKS) * 8 + warp;

        const float* src  = feat + planeidx * (HH*WW);
        float*       fake = out + FAKE_OFF + planeidx * 144;

        float sum = 0.0f;
        #pragma unroll
        for (int k = 0; k < 7; ++k) {
            const int r = lane + k * 32;
            if (r < HH*WW) {
                const float v = src[r];
                sum += v;
                const int y = r / WW;
                const int x = r - y * WW;
                if (y >= 1 && y <= 12 && x >= 1 && x <= 12)
                    fake[(y-1)*12 + (x-1)] = v;
            }
        }
        #pragma unroll
        for (int o = 16; o; o >>= 1)
            sum += __shfl_down_sync(0xFFFFFFFFu, sum, o);
        if (lane == 0)
            out[SNODE_OFF + planeidx] = sum * (1.0f / 196.0f);
        return;
    }

    // -------------------------- RoI branch (box pair) ----------------------
    float* planeA = sm;                          // 32 * PSTR
    float* planeB = sm + CHT * PSTR;             // 32 * PSTR
    float* outsm  = sm + 2 * CHT * PSTR;         // 32 * 49 (shared A then B)

    const int tid  = threadIdx.x;
    const int warp = tid >> 5, lane = tid & 31;
    const int pair = blockIdx.x / TILES;
    const int c0   = (blockIdx.x % TILES) * CHT;
    const int cw   = warp * 4;
    const int nA   = pair * 2, nB = nA + 1;

    // ---- geometry (coords >= 0; upper clamp only) ----
    const float Abx1 = boxes[nA*4+0]*SCALE, Aby1 = boxes[nA*4+1]*SCALE;
    const float Abx2 = boxes[nA*4+2]*SCALE, Aby2 = boxes[nA*4+3]*SCALE;
    const float Bbx1 = boxes[nB*4+0]*SCALE, Bby1 = boxes[nB*4+1]*SCALE;
    const float Bbx2 = boxes[nB*4+2]*SCALE, Bby2 = boxes[nB*4+3]*SCALE;

    const int AryO = (int)fminf(Aby1, 13.0f);
    const int AyL  = min((int)fminf(Aby2, 13.0f) + 1, HH-1);
    const int LA   = (AyL - AryO + 1) * WW;      // even, <= 126
    const int BryO = (int)fminf(Bby1, 13.0f);
    const int ByL  = min((int)fminf(Bby2, 13.0f) + 1, HH-1);
    const int LB   = (ByL - BryO + 1) * WW;

    const float* fbaseA = feat + ((size_t)fidx[nA] * CCH + c0) * (HH*WW) + AryO * WW;
    const float* fbaseB = feat + ((size_t)fidx[nB] * CCH + c0) * (HH*WW) + BryO * WW;

    // ---- load phase: both boxes in flight before any wait ----
    {
        const unsigned int smA = (unsigned int)__cvta_generic_to_shared(planeA);
        const unsigned int smB = (unsigned int)__cvta_generic_to_shared(planeB);
        const int LpA = LA >> 1, LpB = LB >> 1;
        #pragma unroll
        for (int c = 0; c < 4; ++c) {
            const float2*      src = (const float2*)(fbaseA + (cw + c) * (HH*WW));
            const unsigned int dst = smA + (unsigned int)((cw + c) * PSTR) * 4u;
            #pragma unroll
            for (int k = 0; k < 2; ++k) {
                const int p = lane + k * 32;
                if (p < LpA) cp_async8(dst + (unsigned int)p * 8u, src + p);
            }
        }
        asm volatile("cp.async.commit_group;\n" ::: "memory");
        #pragma unroll
        for (int c = 0; c < 4; ++c) {
            const float2*      src = (const float2*)(fbaseB + (cw + c) * (HH*WW));
            const unsigned int dst = smB + (unsigned int)((cw + c) * PSTR) * 4u;
            #pragma unroll
            for (int k = 0; k < 2; ++k) {
                const int p = lane + k * 32;
                if (p < LpB) cp_async8(dst + (unsigned int)p * 8u, src + p);
            }
        }
        asm volatile("cp.async.commit_group;\n" ::: "memory");
        // zero-pad 2 floats past each channel span (disjoint from cp.async range)
        if (lane < 8) {
            const int c = lane >> 1, e = lane & 1;
            planeA[(cw + c) * PSTR + LA + e] = 0.0f;
            planeB[(cw + c) * PSTR + LB + e] = 0.0f;
        }
    }

    float* outs_w = outsm + cw * (OUTS*OUTS);

    // ---- box A: wait for group A only (B still in flight) ----
    asm volatile("cp.async.wait_group 1;\n" ::: "memory");
    __syncwarp();
    roi_compute_store(planeA, outs_w,
                      (float4*)(out + ((size_t)nA * CCH + c0 + cw) * (OUTS*OUTS)),
                      cw, lane,
                      Abx1, (Abx2 - Abx1) * (1.0f/7.0f),
                      Aby1, (Aby2 - Aby1) * (1.0f/7.0f), AryO);

    // ---- box B ----
    asm volatile("cp.async.wait_group 0;\n" ::: "memory");
    __syncwarp();
    roi_compute_store(planeB, outs_w,
                      (float4*)(out + ((size_t)nB * CCH + c0 + cw) * (OUTS*OUTS)),
                      cw, lane,
                      Bbx1, (Bbx2 - Bbx1) * (1.0f/7.0f),
                      Bby1, (Bby2 - Bby1) * (1.0f/7.0f), BryO);
}

// ---------------------------------------------------------------------------
extern "C" void kernel_launch(void* const* d_in, const int* in_sizes, int n_in,
                              void* d_out, int out_size)
{
    const float* feat  = (const float*)d_in[0];
    const float* boxes = (const float*)d_in[1];
    const int*   fidx  = (const int*)d_in[2];
    float*       out   = (float*)d_out;

    const int roi_smem = (2 * CHT * PSTR + CHT * OUTS * OUTS) * (int)sizeof(float); // 39,552 B
    cudaFuncSetAttribute(fused_kernel,
                         cudaFuncAttributeMaxDynamicSharedMemorySize, roi_smem);

    fused_kernel<<<ROI_BLOCKS + SNODE_BLOCKS, 256, roi_smem>>>(feat, boxes, fidx, out);
}

// round 11
// speedup vs baseline: 1.3062x; 1.3062x over previous
#include <cuda_runtime.h>
#include <cstdint>

// Problem constants (fixed shapes)
#define VF    128            // V*F = 8*16
#define CCH   1024
#define HH    14
#define WW    14
#define NBOX  768
#define GG    8              // grid = OUT_SIZE+1
#define OUTS  7
#define CHT   32             // channels per block tile
#define TILES (CCH / CHT)    // 32
#define PSTR  134            // padded plane stride; EVEN (8B cp.async)
#define SCALE (1.0f/16.0f)

#define ROI_BLOCKS   ((NBOX/2) * TILES)                  // 12288 (2 boxes each)
#define SNODE_BLOCKS ((VF * CCH) / 16)                   // 8192 (2 planes/warp)

#define ROI_COUNT   ((size_t)NBOX * CCH * OUTS * OUTS)   // 38,535,168
#define SNODE_OFF   (ROI_COUNT)
#define FAKE_OFF    (SNODE_OFF + (size_t)VF * CCH)       // 38,666,240

__device__ __forceinline__ void cp_async8(unsigned int smem_dst, const void* gmem_src) {
    asm volatile("cp.async.ca.shared.global [%0], [%1], 8;\n"
                 :: "r"(smem_dst), "l"(gmem_src) : "memory");
}

// ---------------------------------------------------------------------------
// One box for one warp: load its 4 channels into plane, compute, store.
// Identical math to the best (R8) kernel. Warp-local only.
// ---------------------------------------------------------------------------
__device__ __forceinline__ void roi_one_box(
    const float* __restrict__ feat,
    const float* __restrict__ boxes,
    const int*   __restrict__ fidx,
    float*       __restrict__ out,
    float* plane, float* outsm,
    int n, int c0, int cw, int lane)
{
    const float bx1 = boxes[n*4+0]*SCALE, by1 = boxes[n*4+1]*SCALE;
    const float bx2 = boxes[n*4+2]*SCALE, by2 = boxes[n*4+3]*SCALE;

    const int ry0   = (int)floorf(fminf(fmaxf(by1, 0.0f), (float)(HH-1)));
    const int ylast = min((int)floorf(fminf(fmaxf(by2, 0.0f), (float)(HH-1))) + 1, HH-1);
    const int L     = (ylast - ry0 + 1) * WW;    // contiguous span, even, <= 126

    const float* fbase = feat + ((size_t)fidx[n] * CCH + c0) * (HH*WW) + ry0 * WW;

    // ---- load: warp's own 4 channels via 8B cp.async ----
    {
        const unsigned int smem_base = (unsigned int)__cvta_generic_to_shared(plane);
        const int Lp = L >> 1;                       // float2 count, <= 63
        #pragma unroll
        for (int c = 0; c < 4; ++c) {
            const float2*      src = (const float2*)(fbase + (cw + c) * (HH*WW));
            const unsigned int dst = smem_base + (unsigned int)((cw + c) * PSTR) * 4u;
            #pragma unroll
            for (int k = 0; k < 2; ++k) {
                const int p = lane + k * 32;
                if (p < Lp) cp_async8(dst + (unsigned int)p * 8u, src + p);
            }
        }
        asm volatile("cp.async.commit_group;\n" ::: "memory");
        asm volatile("cp.async.wait_group 0;\n" ::: "memory");
        __syncwarp();
    }

    // ---- compute: thread = (channel, gx); row-cached registers ----
    {
        const int gx    = lane & 7;
        const int chsub = lane >> 3;
        const int ch    = cw + chsub;
        const float* pl = plane + ch * PSTR;

        const float xs0 = fminf(fmaxf(bx1 + (float)gx * (1.0f/7.0f) * (bx2 - bx1),
                                      0.0f), (float)(WW-1));
        const int   xa  = (int)floorf(xs0);
        const int   xb  = min(xa + 1, WW-1);
        const float wx  = xs0 - (float)xa;

        int   curA = -1, curB = -1;
        float a0 = 0.f, a1 = 0.f, b0 = 0.f, b1 = 0.f;
        float xs_prev = 0.f;

        #pragma unroll
        for (int gy = 0; gy < GG; ++gy) {
            const float ys = fminf(fmaxf(by1 + (float)gy * (1.0f/7.0f) * (by2 - by1),
                                         0.0f), (float)(HH-1));
            const int y0i = (int)floorf(ys);
            const int y1i = min(y0i + 1, HH-1);
            const float wy = ys - (float)y0i;
            const int rA = y0i - ry0;
            const int rB = y1i - ry0;
            if (rA != curA) {                 // warp-uniform branch
                if (rA == curB) { a0 = b0; a1 = b1; }
                else            { a0 = pl[rA*WW + xa]; a1 = pl[rA*WW + xb]; }
                curA = rA;
            }
            if (rB != curB) {                 // warp-uniform branch
                b0 = pl[rB*WW + xa]; b1 = pl[rB*WW + xb];
                curB = rB;
            }
            const float top = a0 + wx * (a1 - a0);
            const float bot = b0 + wx * (b1 - b0);
            const float g   = top + wy * (bot - top);
            // x-pool: neighbor gx+1 within the 8-lane group
            const float gr   = __shfl_down_sync(0xFFFFFFFFu, g, 1, 8);
            const float xsum = g + gr;
            if (gy > 0 && gx < OUTS)
                outsm[ch * (OUTS*OUTS) + (gy-1) * OUTS + gx] = 0.25f * (xs_prev + xsum);
            xs_prev = xsum;
        }
        __syncwarp();
    }

    // ---- store: warp-local vectorized copy of its 4 channels ----
    {
        const float4* src4 = (const float4*)(outsm + cw * (OUTS*OUTS));
        float4*       dst4 = (float4*)(out + ((size_t)n * CCH + c0 + cw) * (OUTS*OUTS));
        #pragma unroll
        for (int i = lane; i < 49; i += 32)          // 4*49 floats = 49 float4
            dst4[i] = src4[i];
        __syncwarp();                                 // plane/outsm reuse safety
    }
}

// ---------------------------------------------------------------------------
// Fused kernel. Blocks [0, ROI_BLOCKS): RoIAlignAvg, 2 boxes sequentially per
// block (prolog amortized), fully warp-independent (no __syncthreads).
// Remaining blocks: s_node mean + fake_h_s slice, 2 planes per warp.
// ---------------------------------------------------------------------------
__global__ __launch_bounds__(256, 8) void fused_kernel(
    const float* __restrict__ feat,
    const float* __restrict__ boxes,
    const int*   __restrict__ fidx,
    float*       __restrict__ out)
{
    extern __shared__ float sm[];

    if (blockIdx.x >= ROI_BLOCKS) {
        // ---------------- snode + fake_h_s branch (2 planes/warp) ---------
        const int warp = threadIdx.x >> 5;
        const int lane = threadIdx.x & 31;
        const size_t p0 = (size_t)(blockIdx.x - ROI_BLOCKS) * 16 + warp * 2;

        #pragma unroll
        for (int pp = 0; pp < 2; ++pp) {
            const size_t planeidx = p0 + pp;
            const float* src  = feat + planeidx * (HH*WW);
            float*       fake = out + FAKE_OFF + planeidx * 144;

            float sum = 0.0f;
            #pragma unroll
            for (int k = 0; k < 7; ++k) {
                const int r = lane + k * 32;
                if (r < HH*WW) {
                    const float v = src[r];
                    sum += v;
                    const int y = r / WW;
                    const int x = r - y * WW;
                    if (y >= 1 && y <= 12 && x >= 1 && x <= 12)
                        fake[(y-1)*12 + (x-1)] = v;
                }
            }
            #pragma unroll
            for (int o = 16; o; o >>= 1)
                sum += __shfl_down_sync(0xFFFFFFFFu, sum, o);
            if (lane == 0)
                out[SNODE_OFF + planeidx] = sum * (1.0f / 196.0f);
        }
        return;
    }

    // -------------------------- RoI branch (2 boxes, sequential) -----------
    float* plane = sm;                     // CHT * PSTR floats
    float* outsm = sm + CHT * PSTR;        // CHT * 49 floats

    const int tid  = threadIdx.x;
    const int warp = tid >> 5, lane = tid & 31;
    const int pair = blockIdx.x / TILES;
    const int c0   = (blockIdx.x % TILES) * CHT;
    const int cw   = warp * 4;             // warp's first channel in tile

    roi_one_box(feat, boxes, fidx, out, plane, outsm, pair*2,     c0, cw, lane);
    roi_one_box(feat, boxes, fidx, out, plane, outsm, pair*2 + 1, c0, cw, lane);
}

// ---------------------------------------------------------------------------
extern "C" void kernel_launch(void* const* d_in, const int* in_sizes, int n_in,
                              void* d_out, int out_size)
{
    const float* feat  = (const float*)d_in[0];
    const float* boxes = (const float*)d_in[1];
    const int*   fidx  = (const int*)d_in[2];
    float*       out   = (float*)d_out;

    const int roi_smem = (CHT * PSTR + CHT * OUTS * OUTS) * (int)sizeof(float); // 23,424 B
    cudaFuncSetAttribute(fused_kernel,
                         cudaFuncAttributeMaxDynamicSharedMemorySize, roi_smem);

    fused_kernel<<<ROI_BLOCKS + SNODE_BLOCKS, 256, roi_smem>>>(feat, boxes, fidx, out);
}